// round 4
// baseline (speedup 1.0000x reference)
#include <cuda_runtime.h>
#include <cuda_bf16.h>
#include <math.h>
#include <cstdint>

#define Bb 64
#define Ff 256
#define Tt 1024
#define Hh 1024
#define Oo 512
#define RNCTA 64          // recurrence CTAs (<=148, co-resident single wave)
#define NCOL 16           // hidden columns per recurrence CTA
#define KC 256            // k elements per streamed S chunk
#define NCHUNK (Hh / KC)  // 4
#define SSTR 528          // S chunk smem row stride bytes (512 + 16 pad)
#define WSTR 2064         // Wh smem row stride bytes (2048 + 16 pad)
#define CHUNK_BYTES (64 * SSTR)           // 33792
#define OFF_WHI 0
#define OFF_WLO 33024                     // 16 * WSTR
#define OFF_CH  66048
#define SMEM_TOTAL (OFF_CH + 4 * CHUNK_BYTES)   // 201216

typedef unsigned long long ull;

// ---------------- device globals (no allocation allowed) ----------------
__device__ float g_xT[(size_t)Tt * Bb * Ff];          // x as (T,B,F)
__device__ float g_U [(size_t)Tt * Hh * Bb];          // U then fp32 states, [t][h][b]
__device__ __nv_bfloat16 g_WhiT[(size_t)Hh * Hh];     // Wh^T hi  [h][k]
__device__ __nv_bfloat16 g_WloT[(size_t)Hh * Hh];     // Wh^T lo  [h][k]
__device__ __nv_bfloat16 g_Sh[2][(size_t)Bb * Hh];    // state hi, [buf][b][k]
__device__ __nv_bfloat16 g_Sl[2][(size_t)Bb * Hh];    // state lo
__device__ unsigned int g_cnt;                        // grid barrier (back to {0,0}/run)
__device__ unsigned int g_sense;

// ---------------- helpers ----------------
__device__ __forceinline__ uint32_t smem_u32(const void* p) {
    uint32_t a;
    asm("{ .reg .u64 t; cvta.to.shared.u64 t, %1; cvt.u32.u64 %0, t; }" : "=r"(a) : "l"(p));
    return a;
}
__device__ __forceinline__ float ftanh(float x) {
    float xc = fminf(fmaxf(x, -15.0f), 15.0f);
    float e  = __expf(2.0f * xc);
    return __fdividef(e - 1.0f, e + 1.0f);
}
__device__ __forceinline__ ull pk2(float lo, float hi) {
    ull r; asm("mov.b64 %0, {%1, %2};" : "=l"(r) : "f"(lo), "f"(hi)); return r;
}
__device__ __forceinline__ ull ffma2(ull a, ull b, ull c) {
    ull d; asm("fma.rn.f32x2 %0, %1, %2, %3;" : "=l"(d) : "l"(a), "l"(b), "l"(c)); return d;
}
__device__ __forceinline__ float2 upk2(ull v) {
    float2 f; asm("mov.b64 {%0, %1}, %2;" : "=f"(f.x), "=f"(f.y) : "l"(v)); return f;
}

// mma.sync m16n8k16 bf16 -> fp32 (base ISA, works on compute_103)
__device__ __forceinline__ void mma16816(float* d, const uint32_t* a, uint32_t b0, uint32_t b1) {
    asm volatile("mma.sync.aligned.m16n8k16.row.col.f32.bf16.bf16.f32 "
        "{%0,%1,%2,%3}, {%4,%5,%6,%7}, {%8,%9}, {%0,%1,%2,%3};"
        : "+f"(d[0]), "+f"(d[1]), "+f"(d[2]), "+f"(d[3])
        : "r"(a[0]), "r"(a[1]), "r"(a[2]), "r"(a[3]), "r"(b0), "r"(b1));
}
__device__ __forceinline__ void ldsm4(uint32_t* r, uint32_t addr) {
    asm volatile("ldmatrix.sync.aligned.m8n8.x4.shared.b16 {%0,%1,%2,%3}, [%4];"
        : "=r"(r[0]), "=r"(r[1]), "=r"(r[2]), "=r"(r[3]) : "r"(addr));
}
__device__ __forceinline__ void cpasync16(uint32_t dst, const void* src) {
    asm volatile("cp.async.cg.shared.global [%0], [%1], 16;" :: "r"(dst), "l"(src));
}
#define CP_COMMIT() asm volatile("cp.async.commit_group;" ::: "memory")
#define CP_WAIT(n)  asm volatile("cp.async.wait_group %0;" :: "n"(n) : "memory")

// ---------------- grid barrier ----------------
__device__ __forceinline__ void gridbar(unsigned s) {
    __syncthreads();
    if (threadIdx.x == 0) {
        __threadfence();
        unsigned prev = atomicAdd(&g_cnt, 1u);
        if (prev == RNCTA - 1) {
            atomicExch(&g_cnt, 0u);
            __threadfence();
            atomicExch(&g_sense, s);
        } else {
            while (*((volatile unsigned int*)&g_sense) != s) { }
        }
        __threadfence();
    }
    __syncthreads();
}

// ---------------- prep kernels ----------------
__global__ void transpose_x_kernel(const float* __restrict__ x) {
    __shared__ float tile[32][33];
    int b = blockIdx.z, t0 = blockIdx.x * 32, f0 = blockIdx.y * 32;
    const float* xb = x + (size_t)b * Ff * Tt;
    for (int i = threadIdx.y; i < 32; i += 8)
        tile[i][threadIdx.x] = xb[(size_t)(f0 + i) * Tt + t0 + threadIdx.x];
    __syncthreads();
    for (int i = threadIdx.y; i < 32; i += 8)
        g_xT[((size_t)(t0 + i) * Bb + b) * Ff + f0 + threadIdx.x] = tile[threadIdx.x][i];
}

// Wh (k,h) fp32 -> WhT hi/lo bf16 [h][k]
__global__ void whsplit_kernel(const float* __restrict__ Wh) {
    __shared__ float tile[32][33];
    int k0 = blockIdx.x * 32, h0 = blockIdx.y * 32;
    for (int i = threadIdx.y; i < 32; i += 8)
        tile[i][threadIdx.x] = Wh[(size_t)(k0 + i) * Hh + h0 + threadIdx.x];
    __syncthreads();
    for (int i = threadIdx.y; i < 32; i += 8) {
        float w = tile[threadIdx.x][i];
        __nv_bfloat16 hi = __float2bfloat16(w);
        size_t idx = (size_t)(h0 + i) * Hh + k0 + threadIdx.x;
        g_WhiT[idx] = hi;
        g_WloT[idx] = __float2bfloat16(w - __bfloat162float(hi));
    }
}

// U[t][h][b] = bias[h] + sum_f xT[t][b][f] * Wx[f][h]   (f32x2 SIMT GEMM)
__global__ __launch_bounds__(256) void u_gemm_kernel(const float* __restrict__ Wx,
                                                     const float* __restrict__ bias) {
    const int t  = blockIdx.y;
    const int h0 = blockIdx.x * 64;
    __shared__ __align__(16) float As[16][68];
    __shared__ __align__(16) float Bs[16][68];
    const int tid = threadIdx.x;
    const int tx = tid & 15, ty = tid >> 4;
    const int ar = tid >> 4, ac = (tid & 15) * 4;
    const int bbr = tid >> 2, bf = (tid & 3) * 4;
    const float* Xr = g_xT + ((size_t)t * Bb + bbr) * Ff;

    ull acc[4][2];
    #pragma unroll
    for (int i = 0; i < 4; ++i) { acc[i][0] = 0ull; acc[i][1] = 0ull; }
    float4 ra = *(const float4*)(Wx + (size_t)ar * Hh + h0 + ac);
    float4 rb = *(const float4*)(Xr + bf);

    for (int k0 = 0; k0 < Ff; k0 += 16) {
        *(float4*)&As[ar][ac] = ra;
        Bs[bf + 0][bbr] = rb.x; Bs[bf + 1][bbr] = rb.y;
        Bs[bf + 2][bbr] = rb.z; Bs[bf + 3][bbr] = rb.w;
        __syncthreads();
        if (k0 + 16 < Ff) {
            ra = *(const float4*)(Wx + (size_t)(k0 + 16 + ar) * Hh + h0 + ac);
            rb = *(const float4*)(Xr + k0 + 16 + bf);
        }
        #pragma unroll
        for (int kk = 0; kk < 16; ++kk) {
            float4 a = *(const float4*)&As[kk][4 * ty];
            ulonglong2 b2 = *(const ulonglong2*)&Bs[kk][4 * tx];
            float av[4] = {a.x, a.y, a.z, a.w};
            #pragma unroll
            for (int i = 0; i < 4; ++i) {
                ull sp = pk2(av[i], av[i]);
                acc[i][0] = ffma2(sp, b2.x, acc[i][0]);
                acc[i][1] = ffma2(sp, b2.y, acc[i][1]);
            }
        }
        __syncthreads();
    }
    #pragma unroll
    for (int i = 0; i < 4; ++i) {
        float bv = bias[h0 + 4 * ty + i];
        float2 lo = upk2(acc[i][0]), hi = upk2(acc[i][1]);
        float4 v = make_float4(lo.x + bv, lo.y + bv, hi.x + bv, hi.y + bv);
        *(float4*)&g_U[((size_t)t * Hh + h0 + 4 * ty + i) * Bb + 4 * tx] = v;
    }
}

// ---------------- persistent mma.sync recurrence ----------------
__device__ __forceinline__ void load_chunk(uint32_t sb, int buf, int c, int z, int tid) {
    #pragma unroll
    for (int i = 0; i < 16; ++i) {
        int seg = tid + i * 256;                  // 0..4095
        int mat = seg >> 11;                      // 0 hi, 1 lo
        int within = seg & 2047;
        int row = within >> 5, u = within & 31;
        const __nv_bfloat16* src = mat
            ? &g_Sl[z][(size_t)row * Hh + c * KC + u * 8]
            : &g_Sh[z][(size_t)row * Hh + c * KC + u * 8];
        uint32_t dst = sb + OFF_CH + (uint32_t)(buf * 2 + mat) * CHUNK_BYTES
                     + (uint32_t)row * SSTR + (uint32_t)u * 16;
        cpasync16(dst, src);
    }
    CP_COMMIT();
}

__global__ __launch_bounds__(256, 1) void rnn_mma_kernel() {
    extern __shared__ __align__(1024) char smem[];
    const uint32_t sb = smem_u32(smem);
    const int tid  = threadIdx.x;
    const int w    = tid >> 5;
    const int lane = tid & 31;
    const int n0   = blockIdx.x * NCOL;       // global col base of CTA
    const int m0   = (w & 3) * 16;            // warp m-tile (batch rows)
    const int nw   = (w >> 2) * 8;            // warp n-tile within CTA cols

    // stage Wh^T hi/lo slice (rows n0..n0+15) into padded smem
    for (int q = tid; q < 16 * 128; q += 256) {      // 16B units per matrix
        int r = q >> 7, u = q & 127;
        *(float4*)(smem + OFF_WHI + r * WSTR + u * 16) =
            ((const float4*)g_WhiT)[(size_t)(n0 + r) * 128 + u];
        *(float4*)(smem + OFF_WLO + r * WSTR + u * 16) =
            ((const float4*)g_WloT)[(size_t)(n0 + r) * 128 + u];
    }

    // t = 0: state = tanh(U[0]); write fp32 state + bf16 hi/lo
    for (int e = tid; e < NCOL * Bb; e += 256) {
        int h = e >> 6, b = e & 63;
        size_t ui = (size_t)(n0 + h) * Bb + b;
        float v = ftanh(g_U[ui]);
        g_U[ui] = v;
        __nv_bfloat16 hi = __float2bfloat16(v);
        g_Sh[0][(size_t)b * Hh + n0 + h] = hi;
        g_Sl[0][(size_t)b * Hh + n0 + h] = __float2bfloat16(v - __bfloat162float(hi));
    }
    gridbar(1u);

    // per-lane fragment geometry
    const uint32_t rowA  = (uint32_t)(m0 + (lane & 7) + ((lane >> 3) & 1) * 8);
    const uint32_t laneK = (uint32_t)((lane >> 4) * 16);          // bytes
    const uint32_t wBhi  = sb + OFF_WHI + (uint32_t)(nw + (lane & 7)) * WSTR
                         + (uint32_t)((lane >> 3) * 16);
    const uint32_t wBlo  = wBhi + (OFF_WLO - OFF_WHI);
    const int r0 = m0 + (lane >> 2);
    const int cA = n0 + nw + 2 * (lane & 3);

    for (int t = 1; t < Tt; ++t) {
        const int zread  = (t - 1) & 1;
        const int zwrite = t & 1;

        load_chunk(sb, 0, 0, zread, tid);

        // prefetch U[t] for this lane's fragment positions
        float u00 = g_U[((size_t)t * Hh + cA) * Bb + r0];
        float u01 = g_U[((size_t)t * Hh + cA + 1) * Bb + r0];
        float u10 = g_U[((size_t)t * Hh + cA) * Bb + r0 + 8];
        float u11 = g_U[((size_t)t * Hh + cA + 1) * Bb + r0 + 8];

        float acc[4] = {0.f, 0.f, 0.f, 0.f};

        for (int c = 0; c < NCHUNK; ++c) {
            if (c + 1 < NCHUNK) {
                load_chunk(sb, (c + 1) & 1, c + 1, zread, tid);
                CP_WAIT(1);
            } else {
                CP_WAIT(0);
            }
            __syncthreads();
            uint32_t ah = sb + OFF_CH + (uint32_t)((c & 1) * 2) * CHUNK_BYTES
                        + rowA * SSTR + laneK;
            uint32_t al = ah + CHUNK_BYTES;
            #pragma unroll
            for (int kp = 0; kp < KC / 32; ++kp) {
                uint32_t bh[4], bl[4];
                uint32_t kglob2 = (uint32_t)(c * KC + kp * 32) * 2;
                ldsm4(bh, wBhi + kglob2);
                ldsm4(bl, wBlo + kglob2);
                #pragma unroll
                for (int s = 0; s < 2; ++s) {
                    uint32_t ahi[4], alo[4];
                    uint32_t kl2 = (uint32_t)(kp * 32 + s * 16) * 2;
                    ldsm4(ahi, ah + kl2);
                    ldsm4(alo, al + kl2);
                    mma16816(acc, ahi, bh[2 * s], bh[2 * s + 1]);
                    mma16816(acc, ahi, bl[2 * s], bl[2 * s + 1]);
                    mma16816(acc, alo, bh[2 * s], bh[2 * s + 1]);
                }
            }
            __syncthreads();
        }

        // epilogue: +U, tanh, store fp32 state + bf16 hi/lo split
        float s00 = ftanh(u00 + acc[0]);
        float s01 = ftanh(u01 + acc[1]);
        float s10 = ftanh(u10 + acc[2]);
        float s11 = ftanh(u11 + acc[3]);
        g_U[((size_t)t * Hh + cA) * Bb + r0]         = s00;
        g_U[((size_t)t * Hh + cA + 1) * Bb + r0]     = s01;
        g_U[((size_t)t * Hh + cA) * Bb + r0 + 8]     = s10;
        g_U[((size_t)t * Hh + cA + 1) * Bb + r0 + 8] = s11;

        {
            __nv_bfloat16 h0 = __float2bfloat16(s00), h1 = __float2bfloat16(s01);
            __nv_bfloat162 hp; hp.x = h0; hp.y = h1;
            __nv_bfloat162 lp;
            lp.x = __float2bfloat16(s00 - __bfloat162float(h0));
            lp.y = __float2bfloat16(s01 - __bfloat162float(h1));
            *(__nv_bfloat162*)&g_Sh[zwrite][(size_t)r0 * Hh + cA] = hp;
            *(__nv_bfloat162*)&g_Sl[zwrite][(size_t)r0 * Hh + cA] = lp;
        }
        {
            __nv_bfloat16 h0 = __float2bfloat16(s10), h1 = __float2bfloat16(s11);
            __nv_bfloat162 hp; hp.x = h0; hp.y = h1;
            __nv_bfloat162 lp;
            lp.x = __float2bfloat16(s10 - __bfloat162float(h0));
            lp.y = __float2bfloat16(s11 - __bfloat162float(h1));
            *(__nv_bfloat162*)&g_Sh[zwrite][(size_t)(r0 + 8) * Hh + cA] = hp;
            *(__nv_bfloat162*)&g_Sl[zwrite][(size_t)(r0 + 8) * Hh + cA] = lp;
        }
        gridbar((unsigned)((t + 1) & 1));
    }
}

// ---------------- output projection (f32x2 SIMT) ----------------
__global__ __launch_bounds__(256) void out_gemm_kernel(const float* __restrict__ Wout,
                                                       const float* __restrict__ bout,
                                                       float* __restrict__ out) {
    const int t  = blockIdx.y;
    const int o0 = blockIdx.x * 64;
    __shared__ __align__(16) float As[16][68];
    __shared__ __align__(16) float Bs[16][68];
    const int tid = threadIdx.x;
    const int tx = tid & 15, ty = tid >> 4;
    const int r = tid >> 4, c = (tid & 15) * 4;

    ull acc[4][2];
    #pragma unroll
    for (int i = 0; i < 4; ++i) { acc[i][0] = 0ull; acc[i][1] = 0ull; }
    float4 ra = *(const float4*)&g_U[((size_t)t * Hh + r) * Bb + c];
    float4 rb = *(const float4*)(Wout + (size_t)r * Oo + o0 + c);

    for (int k0 = 0; k0 < Hh; k0 += 16) {
        *(float4*)&As[r][c] = ra;
        *(float4*)&Bs[r][c] = rb;
        __syncthreads();
        if (k0 + 16 < Hh) {
            ra = *(const float4*)&g_U[((size_t)t * Hh + k0 + 16 + r) * Bb + c];
            rb = *(const float4*)(Wout + (size_t)(k0 + 16 + r) * Oo + o0 + c);
        }
        #pragma unroll
        for (int kk = 0; kk < 16; ++kk) {
            float4 a = *(const float4*)&As[kk][4 * ty];
            ulonglong2 b2 = *(const ulonglong2*)&Bs[kk][4 * tx];
            float av[4] = {a.x, a.y, a.z, a.w};
            #pragma unroll
            for (int i = 0; i < 4; ++i) {
                ull sp = pk2(av[i], av[i]);
                acc[i][0] = ffma2(sp, b2.x, acc[i][0]);
                acc[i][1] = ffma2(sp, b2.y, acc[i][1]);
            }
        }
        __syncthreads();
    }
    float4 bo = *(const float4*)(bout + o0 + 4 * tx);
    #pragma unroll
    for (int i = 0; i < 4; ++i) {
        float2 lo = upk2(acc[i][0]), hi = upk2(acc[i][1]);
        float4 v = make_float4(lo.x + bo.x, lo.y + bo.y, hi.x + bo.z, hi.y + bo.w);
        int b = 4 * ty + i;
        *(float4*)&out[((size_t)b * Tt + t) * Oo + o0 + 4 * tx] = v;
    }
}

// ---------------- host ----------------
extern "C" void kernel_launch(void* const* d_in, const int* in_sizes, int n_in,
                              void* d_out, int out_size) {
    const float* x    = (const float*)d_in[0];
    const float* Wx   = (const float*)d_in[1];
    const float* Wh   = (const float*)d_in[2];
    const float* bias = (const float*)d_in[3];
    const float* Wout = (const float*)d_in[4];
    const float* bout = (const float*)d_in[5];
    float* out = (float*)d_out;

    cudaFuncSetAttribute(rnn_mma_kernel, cudaFuncAttributeMaxDynamicSharedMemorySize, SMEM_TOTAL);

    transpose_x_kernel<<<dim3(Tt / 32, Ff / 32, Bb), dim3(32, 8)>>>(x);
    whsplit_kernel    <<<dim3(Hh / 32, Hh / 32),     dim3(32, 8)>>>(Wh);
    u_gemm_kernel     <<<dim3(Hh / 64, Tt), 256>>>(Wx, bias);
    rnn_mma_kernel    <<<RNCTA, 256, SMEM_TOTAL>>>();
    out_gemm_kernel   <<<dim3(Oo / 64, Tt), 256>>>(Wout, bout, out);
}

// round 5
// speedup vs baseline: 1.5366x; 1.5366x over previous
#include <cuda_runtime.h>
#include <cuda_bf16.h>
#include <math.h>
#include <cstdint>

#define Bb 64
#define Ff 256
#define Tt 1024
#define Hh 1024
#define Oo 512
#define RNCTA 64          // recurrence CTAs (<=148, co-resident single wave)
#define NCOL 16           // hidden columns per recurrence CTA
#define KC 256            // k elements per streamed S chunk
#define NCHUNK (Hh / KC)  // 4
#define SSTR 528          // S chunk smem row stride bytes (512 + 16 pad)
#define WSTR 2064         // Wh smem row stride bytes (2048 + 16 pad)
#define CHUNK_BYTES (64 * SSTR)           // 33792
#define OFF_WHI 0
#define OFF_WLO 33024                     // 16 * WSTR
#define OFF_CH  66048
#define OFF_RED (OFF_CH + 4 * CHUNK_BYTES)      // 201216
#define SMEM_TOTAL (OFF_RED + 16 * 32 * 16)     // + 8KB reduction = 209408

typedef unsigned long long ull;

// ---------------- device globals (no allocation allowed) ----------------
__device__ float g_xT[(size_t)Tt * Bb * Ff];          // x as (T,B,F)
__device__ float g_U [(size_t)Tt * Hh * Bb];          // U then fp32 states, [t][h][b]
__device__ __nv_bfloat16 g_WhiT[(size_t)Hh * Hh];     // Wh^T hi  [h][k]
__device__ __nv_bfloat16 g_WloT[(size_t)Hh * Hh];     // Wh^T lo  [h][k]
__device__ __nv_bfloat16 g_Sh[2][(size_t)Bb * Hh];    // state hi, [buf][b][k]
__device__ __nv_bfloat16 g_Sl[2][(size_t)Bb * Hh];    // state lo
__device__ unsigned int g_cnt;                        // grid barrier (back to {0,0}/run)
__device__ unsigned int g_sense;

// ---------------- helpers ----------------
__device__ __forceinline__ uint32_t smem_u32(const void* p) {
    uint32_t a;
    asm("{ .reg .u64 t; cvta.to.shared.u64 t, %1; cvt.u32.u64 %0, t; }" : "=r"(a) : "l"(p));
    return a;
}
__device__ __forceinline__ float ftanh(float x) {
    float xc = fminf(fmaxf(x, -15.0f), 15.0f);
    float e  = __expf(2.0f * xc);
    return __fdividef(e - 1.0f, e + 1.0f);
}
__device__ __forceinline__ ull pk2(float lo, float hi) {
    ull r; asm("mov.b64 %0, {%1, %2};" : "=l"(r) : "f"(lo), "f"(hi)); return r;
}
__device__ __forceinline__ ull ffma2(ull a, ull b, ull c) {
    ull d; asm("fma.rn.f32x2 %0, %1, %2, %3;" : "=l"(d) : "l"(a), "l"(b), "l"(c)); return d;
}
__device__ __forceinline__ float2 upk2(ull v) {
    float2 f; asm("mov.b64 {%0, %1}, %2;" : "=f"(f.x), "=f"(f.y) : "l"(v)); return f;
}

// mma.sync m16n8k16 bf16 -> fp32 (base ISA on compute_103)
__device__ __forceinline__ void mma16816(float* d, const uint32_t* a, uint32_t b0, uint32_t b1) {
    asm volatile("mma.sync.aligned.m16n8k16.row.col.f32.bf16.bf16.f32 "
        "{%0,%1,%2,%3}, {%4,%5,%6,%7}, {%8,%9}, {%0,%1,%2,%3};"
        : "+f"(d[0]), "+f"(d[1]), "+f"(d[2]), "+f"(d[3])
        : "r"(a[0]), "r"(a[1]), "r"(a[2]), "r"(a[3]), "r"(b0), "r"(b1));
}
__device__ __forceinline__ void ldsm4(uint32_t* r, uint32_t addr) {
    asm volatile("ldmatrix.sync.aligned.m8n8.x4.shared.b16 {%0,%1,%2,%3}, [%4];"
        : "=r"(r[0]), "=r"(r[1]), "=r"(r[2]), "=r"(r[3]) : "r"(addr));
}
__device__ __forceinline__ void cpasync16(uint32_t dst, const void* src) {
    asm volatile("cp.async.cg.shared.global [%0], [%1], 16;" :: "r"(dst), "l"(src));
}
#define CP_COMMIT() asm volatile("cp.async.commit_group;" ::: "memory")
#define CP_WAIT(n)  asm volatile("cp.async.wait_group %0;" :: "n"(n) : "memory")

// ---------------- grid barrier ----------------
__device__ __forceinline__ void gridbar(unsigned s) {
    __syncthreads();
    if (threadIdx.x == 0) {
        __threadfence();
        unsigned prev = atomicAdd(&g_cnt, 1u);
        if (prev == RNCTA - 1) {
            atomicExch(&g_cnt, 0u);
            __threadfence();
            atomicExch(&g_sense, s);
        } else {
            while (*((volatile unsigned int*)&g_sense) != s) { }
        }
        __threadfence();
    }
    __syncthreads();
}

// ---------------- prep kernels ----------------
__global__ void transpose_x_kernel(const float* __restrict__ x) {
    __shared__ float tile[32][33];
    int b = blockIdx.z, t0 = blockIdx.x * 32, f0 = blockIdx.y * 32;
    const float* xb = x + (size_t)b * Ff * Tt;
    for (int i = threadIdx.y; i < 32; i += 8)
        tile[i][threadIdx.x] = xb[(size_t)(f0 + i) * Tt + t0 + threadIdx.x];
    __syncthreads();
    for (int i = threadIdx.y; i < 32; i += 8)
        g_xT[((size_t)(t0 + i) * Bb + b) * Ff + f0 + threadIdx.x] = tile[threadIdx.x][i];
}

// Wh (k,h) fp32 -> WhT hi/lo bf16 [h][k]
__global__ void whsplit_kernel(const float* __restrict__ Wh) {
    __shared__ float tile[32][33];
    int k0 = blockIdx.x * 32, h0 = blockIdx.y * 32;
    for (int i = threadIdx.y; i < 32; i += 8)
        tile[i][threadIdx.x] = Wh[(size_t)(k0 + i) * Hh + h0 + threadIdx.x];
    __syncthreads();
    for (int i = threadIdx.y; i < 32; i += 8) {
        float w = tile[threadIdx.x][i];
        __nv_bfloat16 hi = __float2bfloat16(w);
        size_t idx = (size_t)(h0 + i) * Hh + k0 + threadIdx.x;
        g_WhiT[idx] = hi;
        g_WloT[idx] = __float2bfloat16(w - __bfloat162float(hi));
    }
}

// U[t][h][b] = bias[h] + sum_f xT[t][b][f] * Wx[f][h]   (f32x2 SIMT GEMM)
__global__ __launch_bounds__(256) void u_gemm_kernel(const float* __restrict__ Wx,
                                                     const float* __restrict__ bias) {
    const int t  = blockIdx.y;
    const int h0 = blockIdx.x * 64;
    __shared__ __align__(16) float As[16][68];
    __shared__ __align__(16) float Bs[16][68];
    const int tid = threadIdx.x;
    const int tx = tid & 15, ty = tid >> 4;
    const int ar = tid >> 4, ac = (tid & 15) * 4;
    const int bbr = tid >> 2, bf = (tid & 3) * 4;
    const float* Xr = g_xT + ((size_t)t * Bb + bbr) * Ff;

    ull acc[4][2];
    #pragma unroll
    for (int i = 0; i < 4; ++i) { acc[i][0] = 0ull; acc[i][1] = 0ull; }
    float4 ra = *(const float4*)(Wx + (size_t)ar * Hh + h0 + ac);
    float4 rb = *(const float4*)(Xr + bf);

    for (int k0 = 0; k0 < Ff; k0 += 16) {
        *(float4*)&As[ar][ac] = ra;
        Bs[bf + 0][bbr] = rb.x; Bs[bf + 1][bbr] = rb.y;
        Bs[bf + 2][bbr] = rb.z; Bs[bf + 3][bbr] = rb.w;
        __syncthreads();
        if (k0 + 16 < Ff) {
            ra = *(const float4*)(Wx + (size_t)(k0 + 16 + ar) * Hh + h0 + ac);
            rb = *(const float4*)(Xr + k0 + 16 + bf);
        }
        #pragma unroll
        for (int kk = 0; kk < 16; ++kk) {
            float4 a = *(const float4*)&As[kk][4 * ty];
            ulonglong2 b2 = *(const ulonglong2*)&Bs[kk][4 * tx];
            float av[4] = {a.x, a.y, a.z, a.w};
            #pragma unroll
            for (int i = 0; i < 4; ++i) {
                ull sp = pk2(av[i], av[i]);
                acc[i][0] = ffma2(sp, b2.x, acc[i][0]);
                acc[i][1] = ffma2(sp, b2.y, acc[i][1]);
            }
        }
        __syncthreads();
    }
    #pragma unroll
    for (int i = 0; i < 4; ++i) {
        float bv = bias[h0 + 4 * ty + i];
        float2 lo = upk2(acc[i][0]), hi = upk2(acc[i][1]);
        float4 v = make_float4(lo.x + bv, lo.y + bv, hi.x + bv, hi.y + bv);
        *(float4*)&g_U[((size_t)t * Hh + h0 + 4 * ty + i) * Bb + 4 * tx] = v;
    }
}

// ---------------- persistent mma.sync recurrence (512 thr, split-K warps) ----------------
__device__ __forceinline__ void load_chunk(uint32_t sb, int buf, int c, int z, int tid) {
    #pragma unroll
    for (int i = 0; i < 8; ++i) {
        int seg = tid + i * 512;                  // 0..4095
        int mat = seg >> 11;                      // 0 hi, 1 lo
        int within = seg & 2047;
        int row = within >> 5, u = within & 31;
        const __nv_bfloat16* src = mat
            ? &g_Sl[z][(size_t)row * Hh + c * KC + u * 8]
            : &g_Sh[z][(size_t)row * Hh + c * KC + u * 8];
        uint32_t dst = sb + OFF_CH + (uint32_t)(buf * 2 + mat) * CHUNK_BYTES
                     + (uint32_t)row * SSTR + (uint32_t)u * 16;
        cpasync16(dst, src);
    }
    CP_COMMIT();
}

__global__ __launch_bounds__(512, 1) void rnn_mma_kernel() {
    extern __shared__ __align__(1024) char smem[];
    const uint32_t sb = smem_u32(smem);
    const int tid   = threadIdx.x;
    const int w     = tid >> 5;
    const int lane  = tid & 31;
    const int tile  = w & 7;                  // 8 output tiles
    const int khalf = w >> 3;                 // 0: even 32-k strips, 1: odd
    const int n0    = blockIdx.x * NCOL;
    const int m0    = (tile & 3) * 16;
    const int nw    = (tile >> 2) * 8;

    // stage Wh^T hi/lo slice (rows n0..n0+15)
    for (int q = tid; q < 16 * 128; q += 512) {
        int r = q >> 7, u = q & 127;
        *(float4*)(smem + OFF_WHI + r * WSTR + u * 16) =
            ((const float4*)g_WhiT)[(size_t)(n0 + r) * 128 + u];
        *(float4*)(smem + OFF_WLO + r * WSTR + u * 16) =
            ((const float4*)g_WloT)[(size_t)(n0 + r) * 128 + u];
    }

    // t = 0: state = tanh(U[0])
    for (int e = tid; e < NCOL * Bb; e += 512) {
        int h = e >> 6, b = e & 63;
        size_t ui = (size_t)(n0 + h) * Bb + b;
        float v = ftanh(g_U[ui]);
        g_U[ui] = v;
        __nv_bfloat16 hi = __float2bfloat16(v);
        g_Sh[0][(size_t)b * Hh + n0 + h] = hi;
        g_Sl[0][(size_t)b * Hh + n0 + h] = __float2bfloat16(v - __bfloat162float(hi));
    }
    gridbar(1u);

    // per-lane fragment geometry
    const uint32_t rowA  = (uint32_t)(m0 + (lane & 7) + ((lane >> 3) & 1) * 8);
    const uint32_t laneK = (uint32_t)((lane >> 4) * 16);          // bytes
    const uint32_t wBhi  = sb + OFF_WHI + (uint32_t)(nw + (lane & 7)) * WSTR
                         + (uint32_t)((lane >> 3) * 16);
    const uint32_t wBlo  = wBhi + (OFF_WLO - OFF_WHI);
    const int r0 = m0 + (lane >> 2);
    const int cA = n0 + nw + 2 * (lane & 3);

    for (int t = 1; t < Tt; ++t) {
        const int zread  = (t - 1) & 1;
        const int zwrite = t & 1;

        load_chunk(sb, 0, 0, zread, tid);

        // prefetch U[t] for epilogue lanes (warps 0-7 only)
        float u00, u01, u10, u11;
        if (khalf == 0) {
            u00 = g_U[((size_t)t * Hh + cA) * Bb + r0];
            u01 = g_U[((size_t)t * Hh + cA + 1) * Bb + r0];
            u10 = g_U[((size_t)t * Hh + cA) * Bb + r0 + 8];
            u11 = g_U[((size_t)t * Hh + cA + 1) * Bb + r0 + 8];
        }

        // three independent accumulator chains (hi*hi, hi*lo, lo*hi)
        float ahh[4] = {0.f, 0.f, 0.f, 0.f};
        float ahl[4] = {0.f, 0.f, 0.f, 0.f};
        float alh[4] = {0.f, 0.f, 0.f, 0.f};

        for (int c = 0; c < NCHUNK; ++c) {
            if (c + 1 < NCHUNK) {
                load_chunk(sb, (c + 1) & 1, c + 1, zread, tid);
                CP_WAIT(1);
            } else {
                CP_WAIT(0);
            }
            __syncthreads();
            uint32_t ah = sb + OFF_CH + (uint32_t)((c & 1) * 2) * CHUNK_BYTES
                        + rowA * SSTR + laneK;
            uint32_t al = ah + CHUNK_BYTES;
            // this warp handles 32-k strips kp = khalf, khalf+2, ... (4 of 8)
            #pragma unroll
            for (int kq = 0; kq < 4; ++kq) {
                int kp = khalf + 2 * kq;
                uint32_t bh[4], bl[4];
                uint32_t kglob2 = (uint32_t)(c * KC + kp * 32) * 2;
                ldsm4(bh, wBhi + kglob2);
                ldsm4(bl, wBlo + kglob2);
                #pragma unroll
                for (int s = 0; s < 2; ++s) {
                    uint32_t ahi[4], alo[4];
                    uint32_t kl2 = (uint32_t)(kp * 32 + s * 16) * 2;
                    ldsm4(ahi, ah + kl2);
                    ldsm4(alo, al + kl2);
                    mma16816(ahh, ahi, bh[2 * s], bh[2 * s + 1]);
                    mma16816(ahl, ahi, bl[2 * s], bl[2 * s + 1]);
                    mma16816(alh, alo, bh[2 * s], bh[2 * s + 1]);
                }
            }
            __syncthreads();
        }

        // combine the 3 chains; khalf=1 warps publish partials to smem
        float acc[4];
        #pragma unroll
        for (int i = 0; i < 4; ++i) acc[i] = ahh[i] + ahl[i] + alh[i];

        if (khalf == 1) {
            *(float4*)(smem + OFF_RED + (uint32_t)(tile * 32 + lane) * 16) =
                make_float4(acc[0], acc[1], acc[2], acc[3]);
        }
        __syncthreads();

        if (khalf == 0) {
            float4 p = *(const float4*)(smem + OFF_RED + (uint32_t)(tile * 32 + lane) * 16);
            float s00 = ftanh(u00 + acc[0] + p.x);
            float s01 = ftanh(u01 + acc[1] + p.y);
            float s10 = ftanh(u10 + acc[2] + p.z);
            float s11 = ftanh(u11 + acc[3] + p.w);
            g_U[((size_t)t * Hh + cA) * Bb + r0]         = s00;
            g_U[((size_t)t * Hh + cA + 1) * Bb + r0]     = s01;
            g_U[((size_t)t * Hh + cA) * Bb + r0 + 8]     = s10;
            g_U[((size_t)t * Hh + cA + 1) * Bb + r0 + 8] = s11;
            {
                __nv_bfloat16 h0 = __float2bfloat16(s00), h1 = __float2bfloat16(s01);
                __nv_bfloat162 hp; hp.x = h0; hp.y = h1;
                __nv_bfloat162 lp;
                lp.x = __float2bfloat16(s00 - __bfloat162float(h0));
                lp.y = __float2bfloat16(s01 - __bfloat162float(h1));
                *(__nv_bfloat162*)&g_Sh[zwrite][(size_t)r0 * Hh + cA] = hp;
                *(__nv_bfloat162*)&g_Sl[zwrite][(size_t)r0 * Hh + cA] = lp;
            }
            {
                __nv_bfloat16 h0 = __float2bfloat16(s10), h1 = __float2bfloat16(s11);
                __nv_bfloat162 hp; hp.x = h0; hp.y = h1;
                __nv_bfloat162 lp;
                lp.x = __float2bfloat16(s10 - __bfloat162float(h0));
                lp.y = __float2bfloat16(s11 - __bfloat162float(h1));
                *(__nv_bfloat162*)&g_Sh[zwrite][(size_t)(r0 + 8) * Hh + cA] = hp;
                *(__nv_bfloat162*)&g_Sl[zwrite][(size_t)(r0 + 8) * Hh + cA] = lp;
            }
        }
        gridbar((unsigned)((t + 1) & 1));
    }
}

// ---------------- output projection (f32x2 SIMT) ----------------
__global__ __launch_bounds__(256) void out_gemm_kernel(const float* __restrict__ Wout,
                                                       const float* __restrict__ bout,
                                                       float* __restrict__ out) {
    const int t  = blockIdx.y;
    const int o0 = blockIdx.x * 64;
    __shared__ __align__(16) float As[16][68];
    __shared__ __align__(16) float Bs[16][68];
    const int tid = threadIdx.x;
    const int tx = tid & 15, ty = tid >> 4;
    const int r = tid >> 4, c = (tid & 15) * 4;

    ull acc[4][2];
    #pragma unroll
    for (int i = 0; i < 4; ++i) { acc[i][0] = 0ull; acc[i][1] = 0ull; }
    float4 ra = *(const float4*)&g_U[((size_t)t * Hh + r) * Bb + c];
    float4 rb = *(const float4*)(Wout + (size_t)r * Oo + o0 + c);

    for (int k0 = 0; k0 < Hh; k0 += 16) {
        *(float4*)&As[r][c] = ra;
        *(float4*)&Bs[r][c] = rb;
        __syncthreads();
        if (k0 + 16 < Hh) {
            ra = *(const float4*)&g_U[((size_t)t * Hh + k0 + 16 + r) * Bb + c];
            rb = *(const float4*)(Wout + (size_t)(k0 + 16 + r) * Oo + o0 + c);
        }
        #pragma unroll
        for (int kk = 0; kk < 16; ++kk) {
            float4 a = *(const float4*)&As[kk][4 * ty];
            ulonglong2 b2 = *(const ulonglong2*)&Bs[kk][4 * tx];
            float av[4] = {a.x, a.y, a.z, a.w};
            #pragma unroll
            for (int i = 0; i < 4; ++i) {
                ull sp = pk2(av[i], av[i]);
                acc[i][0] = ffma2(sp, b2.x, acc[i][0]);
                acc[i][1] = ffma2(sp, b2.y, acc[i][1]);
            }
        }
        __syncthreads();
    }
    float4 bo = *(const float4*)(bout + o0 + 4 * tx);
    #pragma unroll
    for (int i = 0; i < 4; ++i) {
        float2 lo = upk2(acc[i][0]), hi = upk2(acc[i][1]);
        float4 v = make_float4(lo.x + bo.x, lo.y + bo.y, hi.x + bo.z, hi.y + bo.w);
        int b = 4 * ty + i;
        *(float4*)&out[((size_t)b * Tt + t) * Oo + o0 + 4 * tx] = v;
    }
}

// ---------------- host ----------------
extern "C" void kernel_launch(void* const* d_in, const int* in_sizes, int n_in,
                              void* d_out, int out_size) {
    const float* x    = (const float*)d_in[0];
    const float* Wx   = (const float*)d_in[1];
    const float* Wh   = (const float*)d_in[2];
    const float* bias = (const float*)d_in[3];
    const float* Wout = (const float*)d_in[4];
    const float* bout = (const float*)d_in[5];
    float* out = (float*)d_out;

    cudaFuncSetAttribute(rnn_mma_kernel, cudaFuncAttributeMaxDynamicSharedMemorySize, SMEM_TOTAL);

    transpose_x_kernel<<<dim3(Tt / 32, Ff / 32, Bb), dim3(32, 8)>>>(x);
    whsplit_kernel    <<<dim3(Hh / 32, Hh / 32),     dim3(32, 8)>>>(Wh);
    u_gemm_kernel     <<<dim3(Hh / 64, Tt), 256>>>(Wx, bias);
    rnn_mma_kernel    <<<RNCTA, 512, SMEM_TOTAL>>>();
    out_gemm_kernel   <<<dim3(Oo / 64, Tt), 256>>>(Wout, bout, out);
}